// round 5
// baseline (speedup 1.0000x reference)
#include <cuda_runtime.h>
#include <cuda_bf16.h>
#include <math.h>

// Problem constants
#define NTOK   8192
#define DIM    256
#define HH     8
#define HD     32
#define WW     64
#define NW     128          // NTOK / WW
#define T6     216          // 3*40 + 3*32
#define QSCALE 0.17677669529663687f   // 32^-0.5

typedef unsigned long long u64;

// ---- packed f32x2 helpers (sm_100+) ----
__device__ __forceinline__ void ffma2(u64 &c, u64 a, u64 b) {
    asm("fma.rn.f32x2 %0, %1, %2, %0;" : "+l"(c) : "l"(a), "l"(b));
}
__device__ __forceinline__ u64 pk2(float lo, float hi) {
    u64 r; asm("mov.b64 %0, {%1, %2};" : "=l"(r) : "f"(lo), "f"(hi)); return r;
}
__device__ __forceinline__ float2 up2(u64 v) {
    float2 r; asm("mov.b64 {%0, %1}, %2;" : "=f"(r.x), "=f"(r.y) : "l"(v)); return r;
}
__device__ __forceinline__ float hsum2(u64 v) { float2 p = up2(v); return p.x + p.y; }

// Global scratch (static device allocations -- allowed)
__device__ float g_q[NTOK * DIM];
__device__ float g_k[NTOK * DIM];
__device__ float g_v[NTOK * DIM];
__device__ float g_att[NTOK * DIM];

// ---------------------------------------------------------------------------
// GEMM core: C[M,N] tile 128x64, BK=16, 256 threads.
// A row-pairs loaded as u64 (no MOV), B duplicated via 4 pk2 per k.
// ---------------------------------------------------------------------------
struct GemmOut { float4 lo, hi; };  // two consecutive rows' 4 cols

template <bool IS_QKV>
__device__ __forceinline__ void gemm_128x64(
    const float* __restrict__ Arow0, const float* __restrict__ Brow0,
    const float* __restrict__ bias, float* __restrict__ out_plain,
    int m0, int n0, int tid)
{
    __shared__ __align__(16) float As[16][132];
    __shared__ __align__(16) float Bs[16][68];
    const int tx = tid & 15, ty = tid >> 4;
    const int alr = tid >> 1, alc = (tid & 1) * 8;   // A: 128 rows x 16
    const int blr = tid >> 2, blc = (tid & 3) * 4;   // B: 64 rows x 16

    u64 c2[4][4];
#pragma unroll
    for (int p = 0; p < 4; p++)
#pragma unroll
        for (int j = 0; j < 4; j++) c2[p][j] = pk2(0.f, 0.f);

    const float* Ap = Arow0 + alr * 256 + alc;
    const float* Bp = Brow0 + blr * 256 + blc;

    for (int kk = 0; kk < 256; kk += 16) {
        float4 a0 = *(const float4*)(Ap + kk);
        float4 a1 = *(const float4*)(Ap + kk + 4);
        float4 b0 = *(const float4*)(Bp + kk);
        __syncthreads();
        As[alc + 0][alr] = a0.x; As[alc + 1][alr] = a0.y;
        As[alc + 2][alr] = a0.z; As[alc + 3][alr] = a0.w;
        As[alc + 4][alr] = a1.x; As[alc + 5][alr] = a1.y;
        As[alc + 6][alr] = a1.z; As[alc + 7][alr] = a1.w;
        Bs[blc + 0][blr] = b0.x; Bs[blc + 1][blr] = b0.y;
        Bs[blc + 2][blr] = b0.z; Bs[blc + 3][blr] = b0.w;
        __syncthreads();
#pragma unroll
        for (int k = 0; k < 16; k++) {
            ulonglong2 ap0 = *(const ulonglong2*)&As[k][ty * 4];
            ulonglong2 ap1 = *(const ulonglong2*)&As[k][64 + ty * 4];
            float4 bv = *(const float4*)&Bs[k][tx * 4];
            u64 ap[4] = {ap0.x, ap0.y, ap1.x, ap1.y};
            u64 bd[4] = {pk2(bv.x, bv.x), pk2(bv.y, bv.y),
                         pk2(bv.z, bv.z), pk2(bv.w, bv.w)};
#pragma unroll
            for (int p = 0; p < 4; p++)
#pragma unroll
                for (int j = 0; j < 4; j++) ffma2(c2[p][j], ap[p], bd[j]);
        }
    }

    // epilogue: pair p covers rows {base, base+1}
    const int n = n0 + tx * 4;
    float4 b4 = *(const float4*)&bias[n];
#pragma unroll
    for (int p = 0; p < 4; p++) {
        int mlo = m0 + ((p < 2) ? (ty * 4 + p * 2) : (64 + ty * 4 + (p - 2) * 2));
        float2 u0 = up2(c2[p][0]), u1 = up2(c2[p][1]);
        float2 u2 = up2(c2[p][2]), u3 = up2(c2[p][3]);
        float4 olo = {u0.x + b4.x, u1.x + b4.y, u2.x + b4.z, u3.x + b4.w};
        float4 ohi = {u0.y + b4.x, u1.y + b4.y, u2.y + b4.z, u3.y + b4.w};
        if (IS_QKV) {
            int s = n >> 8, col = n & 255;
            float* dst = (s == 0) ? g_q : (s == 1) ? g_k : g_v;
            if (s == 0) {
                olo.x *= QSCALE; olo.y *= QSCALE; olo.z *= QSCALE; olo.w *= QSCALE;
                ohi.x *= QSCALE; ohi.y *= QSCALE; ohi.z *= QSCALE; ohi.w *= QSCALE;
            }
            *(float4*)&dst[mlo * 256 + col]       = olo;
            *(float4*)&dst[(mlo + 1) * 256 + col] = ohi;
        } else {
            *(float4*)&out_plain[mlo * 256 + n]       = olo;
            *(float4*)&out_plain[(mlo + 1) * 256 + n] = ohi;
        }
    }
}

__global__ __launch_bounds__(256) void qkv_gemm_kernel(
    const float* __restrict__ A, const float* __restrict__ Wt,
    const float* __restrict__ bias)
{
    gemm_128x64<true>(A + blockIdx.x * 128 * 256, Wt + blockIdx.y * 64 * 256,
                      bias, nullptr, blockIdx.x * 128, blockIdx.y * 64,
                      threadIdx.x);
}

__global__ __launch_bounds__(256) void proj_gemm_kernel(
    const float* __restrict__ Wt, const float* __restrict__ bias,
    float* __restrict__ out)
{
    gemm_128x64<false>(g_att + blockIdx.x * 128 * 256, Wt + blockIdx.y * 64 * 256,
                       bias, out, blockIdx.x * 128, blockIdx.y * 64,
                       threadIdx.x);
}

// ---------------------------------------------------------------------------
// Attention kernel: one block per (window, head). 512 threads (16 warps).
// Shared layout (floats), total 53248 floats = 212992 B:
//   scw   [64*6]    @ 0
//   sq    [64*36]   @ 384
//   sk    [64*36]   @ 2688
//   svT   [32*68]   @ 4992     (d-major)
//   stabQ [216*32]  @ 7168     (dead after Dq/Dk; s_idx u64[4096] aliases)
//   stabK [216*32]  @ 14080
//   sdq   [64*220]  @ 20992    (dead after logits; sat aliases)
//   sdk   [64*220]  @ 35072    (dead after logits; vtabT aliases, str 220)
//   slog  [64*64]   @ 49152
// ---------------------------------------------------------------------------
#define SM_FLOATS 53248
#define SMEM_BYTES (SM_FLOATS * 4)

__global__ __launch_bounds__(512) void attn_kernel(
    const float* __restrict__ n_coords,
    const float* __restrict__ qx, const float* __restrict__ kx,
    const float* __restrict__ vx,
    const float* __restrict__ qr, const float* __restrict__ kr,
    const float* __restrict__ vr)
{
    extern __shared__ __align__(16) float sm[];
    float* scw   = sm;
    float* sq    = sm + 384;
    float* sk    = sm + 2688;
    float* svT   = sm + 4992;
    float* stabQ = sm + 7168;
    float* stabK = sm + 14080;
    float* sdq   = sm + 20992;  // stride 220
    float* sdk   = sm + 35072;  // stride 220
    float* slog  = sm + 49152;
    float* sat   = sdq;                       // bins, aliases after logits
    float* vtabT = sdk;                       // 32 rows str 220, after logits
    u64*   s_idx = (u64*)(sm + 7168);         // u64[64*64]=32KB in stabQ/K

    const int nb = blockIdx.x, h = blockIdx.y;
    const int tid = threadIdx.x;
    const int l = tid & 31, w = tid >> 5;
    const int tok0 = nb * WW;

    // ---- load coords, q, k, v(T), both tables ----
    for (int s = tid; s < WW * 6; s += 512) {
        int i = s / 6, c = s % 6;
        scw[s] = n_coords[(tok0 + i) * 6 + c] * (c < 3 ? 4.0f : 8.0f);
    }
    for (int s = tid; s < WW * HD; s += 512) {
        int i = s >> 5, d = s & 31;
        int g = (tok0 + i) * 256 + h * 32 + d;
        sq[i * 36 + d]  = g_q[g];
        sk[i * 36 + d]  = g_k[g];
        svT[d * 68 + i] = g_v[g];
    }
    for (int s = tid; s < T6 * HD; s += 512) {
        int t = s >> 5, d = s & 31;
        stabQ[s] = (t < 120) ? qx[(t * 8 + h) * 32 + d]
                             : qr[((t - 120) * 8 + h) * 32 + d];
        stabK[s] = (t < 120) ? kx[(t * 8 + h) * 32 + d]
                             : kr[((t - 120) * 8 + h) * 32 + d];
    }
    __syncthreads();

    // ---- Dq / Dk : i = tid&63, each of 8 groups covers 27 t ----
    {
        const int i = tid & 63, grp = tid >> 6;
        const int t0 = grp * 27, t1 = t0 + 27;
        {
            const ulonglong2* q2p = (const ulonglong2*)(sq + i * 36);
            ulonglong2 a2[8];
#pragma unroll
            for (int d2 = 0; d2 < 8; d2++) a2[d2] = q2p[d2];
            for (int t = t0; t < t1; t++) {
                const ulonglong2* tv = (const ulonglong2*)(stabQ + t * 32);
                u64 acc = pk2(0.f, 0.f);
#pragma unroll
                for (int d2 = 0; d2 < 8; d2++) {
                    ulonglong2 tvv = tv[d2];
                    ffma2(acc, a2[d2].x, tvv.x);
                    ffma2(acc, a2[d2].y, tvv.y);
                }
                sdq[i * 220 + t] = hsum2(acc);
            }
        }
        {
            const ulonglong2* k2p = (const ulonglong2*)(sk + i * 36);
            ulonglong2 a2[8];
#pragma unroll
            for (int d2 = 0; d2 < 8; d2++) a2[d2] = k2p[d2];
            for (int t = t0; t < t1; t++) {
                const ulonglong2* tv = (const ulonglong2*)(stabK + t * 32);
                u64 acc = pk2(0.f, 0.f);
#pragma unroll
                for (int d2 = 0; d2 < 8; d2++) {
                    ulonglong2 tvv = tv[d2];
                    ffma2(acc, a2[d2].x, tvv.x);
                    ffma2(acc, a2[d2].y, tvv.y);
                }
                sdk[i * 220 + t] = hsum2(acc);
            }
        }
    }
    __syncthreads();

    // ---- logits (4 rows per warp) + idx pack into s_idx ----
    {
        const int basec[6] = {0, 40, 80, 120, 152, 184};
        const int offc[6]  = {20, 20, 20, 16, 16, 16};
        const int hic[6]   = {39, 39, 39, 31, 31, 31};
#pragma unroll
        for (int r = 0; r < 4; r++) {
            int i = w * 4 + r;
            float ci[6];
#pragma unroll
            for (int c = 0; c < 6; c++) ci[c] = scw[i * 6 + c];
            const ulonglong2* q2p = (const ulonglong2*)(sq + i * 36);
            ulonglong2 q2[8];
#pragma unroll
            for (int d2 = 0; d2 < 8; d2++) q2[d2] = q2p[d2];
#pragma unroll
            for (int jj = 0; jj < 2; jj++) {
                int j = l + jj * 32;
                const ulonglong2* k2p = (const ulonglong2*)(sk + j * 36);
                u64 acc2 = pk2(0.f, 0.f);
#pragma unroll
                for (int d2 = 0; d2 < 8; d2++) {
                    ulonglong2 kv = k2p[d2];
                    ffma2(acc2, q2[d2].x, kv.x);
                    ffma2(acc2, q2[d2].y, kv.y);
                }
                float acc = hsum2(acc2);
                u64 pack = 0;
#pragma unroll
                for (int c = 0; c < 6; c++) {
                    int id = (int)floorf(ci[c] - scw[j * 6 + c]) + offc[c];
                    id = min(max(id, 0), hic[c]);
                    int t = basec[c] + id;
                    acc += sdq[i * 220 + t] + sdk[j * 220 + t];
                    pack |= (u64)t << (8 * c);
                }
                slog[i * 64 + j] = acc;
                s_idx[i * 64 + j] = pack;
            }
        }
    }
    __syncthreads();   // all logits reads of sdq/sdk complete

    // ---- zero bins, load v-table (transposed) into sdk region ----
    for (int s = tid; s < 64 * 220; s += 512) sat[s] = 0.f;
    for (int s = tid; s < T6 * HD; s += 512) {
        int t = s >> 5, d = s & 31;
        float val = (t < 120) ? vx[(t * 8 + h) * 32 + d]
                              : vr[((t - 120) * 8 + h) * 32 + d];
        vtabT[d * 220 + t] = val;
    }
    __syncthreads();

    // ---- fused softmax + binning (own rows per warp) ----
#pragma unroll
    for (int r = 0; r < 4; r++) {
        int i = w * 4 + r;
        float v0 = slog[i * 64 + l], v1 = slog[i * 64 + l + 32];
        float m = fmaxf(v0, v1);
#pragma unroll
        for (int o = 16; o > 0; o >>= 1)
            m = fmaxf(m, __shfl_xor_sync(0xffffffffu, m, o));
        float e0 = __expf(v0 - m), e1 = __expf(v1 - m);
        float s = e0 + e1;
#pragma unroll
        for (int o = 16; o > 0; o >>= 1)
            s += __shfl_xor_sync(0xffffffffu, s, o);
        float inv = 1.0f / s;
        float a0 = e0 * inv, a1 = e1 * inv;
        slog[i * 64 + l]      = a0;
        slog[i * 64 + l + 32] = a1;
        u64 p0 = s_idx[i * 64 + l];
        u64 p1 = s_idx[i * 64 + l + 32];
        float* row = sat + i * 220;
#pragma unroll
        for (int c = 0; c < 6; c++) {
            atomicAdd(row + (int)((p0 >> (8 * c)) & 255u), a0);
            atomicAdd(row + (int)((p1 >> (8 * c)) & 255u), a1);
        }
    }
    __syncwarp();   // this warp's bins + slog visible warp-wide

    // ---- out[i][d] = attn @ v + at @ vtab ; lane = d, v chunks reused x4 rows
    {
        const int i0 = w * 4;
        u64 acc2[4];
#pragma unroll
        for (int r = 0; r < 4; r++) acc2[r] = pk2(0.f, 0.f);

        const ulonglong2* v2p = (const ulonglong2*)(svT + l * 68);
#pragma unroll
        for (int j4 = 0; j4 < 16; j4++) {
            ulonglong2 v2 = v2p[j4];
#pragma unroll
            for (int r = 0; r < 4; r++) {
                ulonglong2 a2 = *(const ulonglong2*)&slog[(i0 + r) * 64 + j4 * 4];
                ffma2(acc2[r], a2.x, v2.x);
                ffma2(acc2[r], a2.y, v2.y);
            }
        }
        const ulonglong2* vt2p = (const ulonglong2*)(vtabT + l * 220);
#pragma unroll
        for (int t4 = 0; t4 < 54; t4++) {
            ulonglong2 v2 = vt2p[t4];
#pragma unroll
            for (int r = 0; r < 4; r++) {
                ulonglong2 a2 = *(const ulonglong2*)&sat[(i0 + r) * 220 + t4 * 4];
                ffma2(acc2[r], a2.x, v2.x);
                ffma2(acc2[r], a2.y, v2.y);
            }
        }
#pragma unroll
        for (int r = 0; r < 4; r++)
            g_att[(tok0 + i0 + r) * 256 + h * 32 + l] = hsum2(acc2[r]);
    }
}

// ---------------------------------------------------------------------------
extern "C" void kernel_launch(void* const* d_in, const int* in_sizes, int n_in,
                              void* d_out, int out_size)
{
    const float* feats    = (const float*)d_in[0];
    const float* n_coords = (const float*)d_in[1];
    const float* qkv_w    = (const float*)d_in[2];
    const float* qkv_b    = (const float*)d_in[3];
    const float* qx       = (const float*)d_in[4];
    const float* kx       = (const float*)d_in[5];
    const float* vx       = (const float*)d_in[6];
    const float* qr       = (const float*)d_in[7];
    const float* kr       = (const float*)d_in[8];
    const float* vr       = (const float*)d_in[9];
    const float* pw       = (const float*)d_in[10];
    const float* pb       = (const float*)d_in[11];
    float* out = (float*)d_out;

    cudaFuncSetAttribute(attn_kernel,
                         cudaFuncAttributeMaxDynamicSharedMemorySize,
                         SMEM_BYTES);

    qkv_gemm_kernel<<<dim3(64, 12), 256>>>(feats, qkv_w, qkv_b);
    attn_kernel<<<dim3(NW, HH), 512, SMEM_BYTES>>>(n_coords, qx, kx, vx,
                                                   qr, kr, vr);
    proj_gemm_kernel<<<dim3(64, 4), 256>>>(pw, pb, out);
}

// round 6
// speedup vs baseline: 1.0862x; 1.0862x over previous
#include <cuda_runtime.h>
#include <cuda_bf16.h>
#include <math.h>

// Problem constants
#define NTOK   8192
#define DIM    256
#define HH     8
#define HD     32
#define WW     64
#define NW     128          // NTOK / WW
#define T6     216          // 3*40 + 3*32
#define QSCALE 0.17677669529663687f   // 32^-0.5

typedef unsigned long long u64;

// ---- packed f32x2 helpers (sm_100+) ----
__device__ __forceinline__ void ffma2(u64 &c, u64 a, u64 b) {
    asm("fma.rn.f32x2 %0, %1, %2, %0;" : "+l"(c) : "l"(a), "l"(b));
}
__device__ __forceinline__ u64 pk2(float lo, float hi) {
    u64 r; asm("mov.b64 %0, {%1, %2};" : "=l"(r) : "f"(lo), "f"(hi)); return r;
}
__device__ __forceinline__ float2 up2(u64 v) {
    float2 r; asm("mov.b64 {%0, %1}, %2;" : "=f"(r.x), "=f"(r.y) : "l"(v)); return r;
}
__device__ __forceinline__ float hsum2(u64 v) { float2 p = up2(v); return p.x + p.y; }

// Global scratch (static device allocations -- allowed)
__device__ float g_q[NTOK * DIM];
__device__ float g_k[NTOK * DIM];
__device__ float g_v[NTOK * DIM];
__device__ float g_att[NTOK * DIM];

// ---------------------------------------------------------------------------
// QKV GEMM (R4 version): BM=128 BN=128 BK=16, 256 threads, 8x8 via f32x2.
// ---------------------------------------------------------------------------
__global__ __launch_bounds__(256) void qkv_gemm_kernel(
    const float* __restrict__ A, const float* __restrict__ Wt,
    const float* __restrict__ bias)
{
    __shared__ __align__(16) float As[16][132];
    __shared__ __align__(16) float Bs[16][132];
    const int m0 = blockIdx.x * 128, n0 = blockIdx.y * 128;
    const int tid = threadIdx.x;
    const int tx = tid & 15, ty = tid >> 4;
    const int lr = tid >> 1, lc = (tid & 1) * 8;

    u64 c2[8][4];
#pragma unroll
    for (int i = 0; i < 8; i++)
#pragma unroll
        for (int j = 0; j < 4; j++) c2[i][j] = pk2(0.f, 0.f);

    const float* Arow = A  + (m0 + lr) * 256 + lc;
    const float* Brow = Wt + (n0 + lr) * 256 + lc;

    for (int kk = 0; kk < 256; kk += 16) {
        float4 a0 = *(const float4*)(Arow + kk);
        float4 a1 = *(const float4*)(Arow + kk + 4);
        float4 b0 = *(const float4*)(Brow + kk);
        float4 b1 = *(const float4*)(Brow + kk + 4);
        __syncthreads();
        As[lc + 0][lr] = a0.x; As[lc + 1][lr] = a0.y;
        As[lc + 2][lr] = a0.z; As[lc + 3][lr] = a0.w;
        As[lc + 4][lr] = a1.x; As[lc + 5][lr] = a1.y;
        As[lc + 6][lr] = a1.z; As[lc + 7][lr] = a1.w;
        Bs[lc + 0][lr] = b0.x; Bs[lc + 1][lr] = b0.y;
        Bs[lc + 2][lr] = b0.z; Bs[lc + 3][lr] = b0.w;
        Bs[lc + 4][lr] = b1.x; Bs[lc + 5][lr] = b1.y;
        Bs[lc + 6][lr] = b1.z; Bs[lc + 7][lr] = b1.w;
        __syncthreads();
#pragma unroll
        for (int k = 0; k < 16; k++) {
            float4 av0 = *(const float4*)&As[k][ty * 4];
            float4 av1 = *(const float4*)&As[k][64 + ty * 4];
            ulonglong2 bl = *(const ulonglong2*)&Bs[k][tx * 4];
            ulonglong2 bh = *(const ulonglong2*)&Bs[k][64 + tx * 4];
            u64 bb[4] = {bl.x, bl.y, bh.x, bh.y};
            float aa[8] = {av0.x, av0.y, av0.z, av0.w,
                           av1.x, av1.y, av1.z, av1.w};
#pragma unroll
            for (int i = 0; i < 8; i++) {
                u64 ad = pk2(aa[i], aa[i]);
#pragma unroll
                for (int j = 0; j < 4; j++) ffma2(c2[i][j], ad, bb[j]);
            }
        }
    }

#pragma unroll
    for (int i = 0; i < 8; i++) {
        int m = m0 + ((i < 4) ? (ty * 4 + i) : (64 + ty * 4 + i - 4));
#pragma unroll
        for (int g = 0; g < 2; g++) {
            int n = n0 + g * 64 + tx * 4;
            float2 p0 = up2(c2[i][g * 2]);
            float2 p1 = up2(c2[i][g * 2 + 1]);
            float4 b4 = *(const float4*)&bias[n];
            float4 o;
            o.x = p0.x + b4.x; o.y = p0.y + b4.y;
            o.z = p1.x + b4.z; o.w = p1.y + b4.w;
            int s = n >> 8, col = n & 255;
            float* dst;
            if (s == 0) {
                o.x *= QSCALE; o.y *= QSCALE; o.z *= QSCALE; o.w *= QSCALE;
                dst = g_q;
            } else if (s == 1) dst = g_k;
            else               dst = g_v;
            *(float4*)&dst[m * 256 + col] = o;
        }
    }
}

// ---------------------------------------------------------------------------
// Projection GEMM (R4 version)
// ---------------------------------------------------------------------------
__global__ __launch_bounds__(256) void proj_gemm_kernel(
    const float* __restrict__ Wt, const float* __restrict__ bias,
    float* __restrict__ out)
{
    __shared__ __align__(16) float As[16][132];
    __shared__ __align__(16) float Bs[16][132];
    const int m0 = blockIdx.x * 128, n0 = blockIdx.y * 128;
    const int tid = threadIdx.x;
    const int tx = tid & 15, ty = tid >> 4;
    const int lr = tid >> 1, lc = (tid & 1) * 8;

    u64 c2[8][4];
#pragma unroll
    for (int i = 0; i < 8; i++)
#pragma unroll
        for (int j = 0; j < 4; j++) c2[i][j] = pk2(0.f, 0.f);

    const float* Arow = g_att + (m0 + lr) * 256 + lc;
    const float* Brow = Wt    + (n0 + lr) * 256 + lc;

    for (int kk = 0; kk < 256; kk += 16) {
        float4 a0 = *(const float4*)(Arow + kk);
        float4 a1 = *(const float4*)(Arow + kk + 4);
        float4 b0 = *(const float4*)(Brow + kk);
        float4 b1 = *(const float4*)(Brow + kk + 4);
        __syncthreads();
        As[lc + 0][lr] = a0.x; As[lc + 1][lr] = a0.y;
        As[lc + 2][lr] = a0.z; As[lc + 3][lr] = a0.w;
        As[lc + 4][lr] = a1.x; As[lc + 5][lr] = a1.y;
        As[lc + 6][lr] = a1.z; As[lc + 7][lr] = a1.w;
        Bs[lc + 0][lr] = b0.x; Bs[lc + 1][lr] = b0.y;
        Bs[lc + 2][lr] = b0.z; Bs[lc + 3][lr] = b0.w;
        Bs[lc + 4][lr] = b1.x; Bs[lc + 5][lr] = b1.y;
        Bs[lc + 6][lr] = b1.z; Bs[lc + 7][lr] = b1.w;
        __syncthreads();
#pragma unroll
        for (int k = 0; k < 16; k++) {
            float4 av0 = *(const float4*)&As[k][ty * 4];
            float4 av1 = *(const float4*)&As[k][64 + ty * 4];
            ulonglong2 bl = *(const ulonglong2*)&Bs[k][tx * 4];
            ulonglong2 bh = *(const ulonglong2*)&Bs[k][64 + tx * 4];
            u64 bb[4] = {bl.x, bl.y, bh.x, bh.y};
            float aa[8] = {av0.x, av0.y, av0.z, av0.w,
                           av1.x, av1.y, av1.z, av1.w};
#pragma unroll
            for (int i = 0; i < 8; i++) {
                u64 ad = pk2(aa[i], aa[i]);
#pragma unroll
                for (int j = 0; j < 4; j++) ffma2(c2[i][j], ad, bb[j]);
            }
        }
    }

#pragma unroll
    for (int i = 0; i < 8; i++) {
        int m = m0 + ((i < 4) ? (ty * 4 + i) : (64 + ty * 4 + i - 4));
#pragma unroll
        for (int g = 0; g < 2; g++) {
            int n = n0 + g * 64 + tx * 4;
            float2 p0 = up2(c2[i][g * 2]);
            float2 p1 = up2(c2[i][g * 2 + 1]);
            float4 b4 = *(const float4*)&bias[n];
            float4 o;
            o.x = p0.x + b4.x; o.y = p0.y + b4.y;
            o.z = p1.x + b4.z; o.w = p1.y + b4.w;
            *(float4*)&out[m * 256 + n] = o;
        }
    }
}

// ---------------------------------------------------------------------------
// Attention kernel: one block per (window, head). 512 threads (16 warps).
// Shared layout (floats), total 52768 floats = 211072 B:
//   scw   [384]       @ 0
//   sq    [64*33]     @ 384     (stride 33: conflict-free per-lane rows)
//   sk    [64*33]     @ 2496
//   svT   [32*65]     @ 4608    (d-major, stride 65)
//   stabQ [216*32]    @ 6688    (dead after Dq/Dk; s_idx u64[4096] aliases)
//   stabK [216*32]    @ 13600
//   sdq   [64*220]    @ 20512   (dead after logits; sat bins alias, str 220)
//   sdk   [64*220]    @ 34592   (dead after logits; vtabT aliases, str 217)
//   slog  [64*64]     @ 48672
// ---------------------------------------------------------------------------
#define SM_FLOATS 52768
#define SMEM_BYTES (SM_FLOATS * 4)

__global__ __launch_bounds__(512) void attn_kernel(
    const float* __restrict__ n_coords,
    const float* __restrict__ qx, const float* __restrict__ kx,
    const float* __restrict__ vx,
    const float* __restrict__ qr, const float* __restrict__ kr,
    const float* __restrict__ vr)
{
    extern __shared__ __align__(16) float sm[];
    float* scw   = sm;
    float* sq    = sm + 384;     // stride 33
    float* sk    = sm + 2496;    // stride 33
    float* svT   = sm + 4608;    // stride 65
    float* stabQ = sm + 6688;
    float* stabK = sm + 13600;
    float* sdq   = sm + 20512;   // stride 220
    float* sdk   = sm + 34592;   // stride 220
    float* slog  = sm + 48672;
    float* sat   = sdq;                  // bins, stride 220 (after logits)
    float* vtabT = sdk;                  // 32 rows, stride 217 (after logits)
    u64*   s_idx = (u64*)(sm + 6688);    // u64[4096] over stabQ/K (after Dq/Dk)

    const int nb = blockIdx.x, h = blockIdx.y;
    const int tid = threadIdx.x;
    const int l = tid & 31, w = tid >> 5;
    const int tok0 = nb * WW;

    // ---- load coords, q, k, v(T), both tables ----
    for (int s = tid; s < WW * 6; s += 512) {
        int i = s / 6, c = s % 6;
        scw[s] = n_coords[(tok0 + i) * 6 + c] * (c < 3 ? 4.0f : 8.0f);
    }
    for (int s = tid; s < WW * HD; s += 512) {
        int i = s >> 5, d = s & 31;
        int g = (tok0 + i) * 256 + h * 32 + d;
        sq[i * 33 + d]  = g_q[g];
        sk[i * 33 + d]  = g_k[g];
        svT[d * 65 + i] = g_v[g];
    }
    for (int s = tid; s < T6 * HD; s += 512) {
        int t = s >> 5, d = s & 31;
        stabQ[s] = (t < 120) ? qx[(t * 8 + h) * 32 + d]
                             : qr[((t - 120) * 8 + h) * 32 + d];
        stabK[s] = (t < 120) ? kx[(t * 8 + h) * 32 + d]
                             : kr[((t - 120) * 8 + h) * 32 + d];
    }
    __syncthreads();

    // ---- Dq / Dk : i = tid&63, each of 8 groups covers 27 t ----
    {
        const int i = tid & 63, grp = tid >> 6;
        const int t0 = grp * 27, t1 = t0 + 27;
        u64 a2[16];
#pragma unroll
        for (int d2 = 0; d2 < 16; d2++)
            a2[d2] = pk2(sq[i * 33 + 2 * d2], sq[i * 33 + 2 * d2 + 1]);
        for (int t = t0; t < t1; t++) {
            const ulonglong2* tv = (const ulonglong2*)(stabQ + t * 32);
            u64 acc = pk2(0.f, 0.f);
#pragma unroll
            for (int d4 = 0; d4 < 8; d4++) {
                ulonglong2 tt = tv[d4];
                ffma2(acc, a2[2 * d4],     tt.x);
                ffma2(acc, a2[2 * d4 + 1], tt.y);
            }
            sdq[i * 220 + t] = hsum2(acc);
        }
#pragma unroll
        for (int d2 = 0; d2 < 16; d2++)
            a2[d2] = pk2(sk[i * 33 + 2 * d2], sk[i * 33 + 2 * d2 + 1]);
        for (int t = t0; t < t1; t++) {
            const ulonglong2* tv = (const ulonglong2*)(stabK + t * 32);
            u64 acc = pk2(0.f, 0.f);
#pragma unroll
            for (int d4 = 0; d4 < 8; d4++) {
                ulonglong2 tt = tv[d4];
                ffma2(acc, a2[2 * d4],     tt.x);
                ffma2(acc, a2[2 * d4 + 1], tt.y);
            }
            sdk[i * 220 + t] = hsum2(acc);
        }
    }
    __syncthreads();

    // ---- logits (4 rows per warp) + idx pack into s_idx ----
    {
        const int basec[6] = {0, 40, 80, 120, 152, 184};
        const int offc[6]  = {20, 20, 20, 16, 16, 16};
        const int hic[6]   = {39, 39, 39, 31, 31, 31};
#pragma unroll
        for (int r = 0; r < 4; r++) {
            int i = w * 4 + r;
            float ci[6];
#pragma unroll
            for (int c = 0; c < 6; c++) ci[c] = scw[i * 6 + c];
            u64 q2[16];
#pragma unroll
            for (int d2 = 0; d2 < 16; d2++)
                q2[d2] = pk2(sq[i * 33 + 2 * d2], sq[i * 33 + 2 * d2 + 1]);
#pragma unroll
            for (int jj = 0; jj < 2; jj++) {
                int j = l + jj * 32;
                const float* krow = sk + j * 33;
                u64 acc2 = pk2(0.f, 0.f);
#pragma unroll
                for (int d2 = 0; d2 < 16; d2++)
                    ffma2(acc2, q2[d2], pk2(krow[2 * d2], krow[2 * d2 + 1]));
                float acc = hsum2(acc2);
                u64 pack = 0;
#pragma unroll
                for (int c = 0; c < 6; c++) {
                    int id = (int)floorf(ci[c] - scw[j * 6 + c]) + offc[c];
                    id = min(max(id, 0), hic[c]);
                    int t = basec[c] + id;
                    acc += sdq[i * 220 + t] + sdk[j * 220 + t];
                    pack |= (u64)t << (8 * c);
                }
                slog[i * 64 + j] = acc;
                s_idx[i * 64 + j] = pack;
            }
        }
    }
    __syncthreads();   // logits reads of sdq/sdk complete; bins may now alias

    // ---- zero bins, load v-table (transposed, stride 217) ----
    for (int s = tid; s < 64 * 220; s += 512) sat[s] = 0.f;
    for (int s = tid; s < T6 * HD; s += 512) {
        int t = s >> 5, d = s & 31;
        float val = (t < 120) ? vx[(t * 8 + h) * 32 + d]
                              : vr[((t - 120) * 8 + h) * 32 + d];
        vtabT[d * 217 + t] = val;
    }
    __syncthreads();

    // ---- softmax (own rows per warp) ----
#pragma unroll
    for (int r = 0; r < 4; r++) {
        int i = w * 4 + r;
        float v0 = slog[i * 64 + l], v1 = slog[i * 64 + l + 32];
        float m = fmaxf(v0, v1);
#pragma unroll
        for (int o = 16; o > 0; o >>= 1)
            m = fmaxf(m, __shfl_xor_sync(0xffffffffu, m, o));
        float e0 = __expf(v0 - m), e1 = __expf(v1 - m);
        float s = e0 + e1;
#pragma unroll
        for (int o = 16; o > 0; o >>= 1)
            s += __shfl_xor_sync(0xffffffffu, s, o);
        float inv = 1.0f / s;
        slog[i * 64 + l]      = e0 * inv;
        slog[i * 64 + l + 32] = e1 * inv;
    }
    __syncwarp();

    // ---- atomic-free binning: lane owns (row, coord) -> disjoint bin range
    if (l < 24) {
        int r = l / 6, c = l % 6;
        int i = w * 4 + r;
        float* row = sat + i * 220;
        const float* lg = slog + i * 64;
        const u64* ip = s_idx + i * 64;
        const int sh = 8 * c;
        for (int j = 0; j < 64; j++) {
            int t = (int)((ip[j] >> sh) & 255u);
            row[t] += lg[j];
        }
    }
    __syncwarp();

    // ---- out[i][d] = attn @ v + at @ vtab ; lane = d ----
    {
        const int i0 = w * 4;
        u64 acc2[4];
#pragma unroll
        for (int r = 0; r < 4; r++) acc2[r] = pk2(0.f, 0.f);

        const float* svrow = svT + l * 65;
        const u64* lg0 = (const u64*)(slog + (i0 + 0) * 64);
        const u64* lg1 = (const u64*)(slog + (i0 + 1) * 64);
        const u64* lg2 = (const u64*)(slog + (i0 + 2) * 64);
        const u64* lg3 = (const u64*)(slog + (i0 + 3) * 64);
#pragma unroll 8
        for (int u = 0; u < 32; u++) {
            u64 v2 = pk2(svrow[2 * u], svrow[2 * u + 1]);
            ffma2(acc2[0], lg0[u], v2);
            ffma2(acc2[1], lg1[u], v2);
            ffma2(acc2[2], lg2[u], v2);
            ffma2(acc2[3], lg3[u], v2);
        }
        const float* vtrow = vtabT + l * 217;
        const u64* b0 = (const u64*)(sat + (i0 + 0) * 220);
        const u64* b1 = (const u64*)(sat + (i0 + 1) * 220);
        const u64* b2 = (const u64*)(sat + (i0 + 2) * 220);
        const u64* b3 = (const u64*)(sat + (i0 + 3) * 220);
#pragma unroll 9
        for (int u = 0; u < 108; u++) {
            u64 v2 = pk2(vtrow[2 * u], vtrow[2 * u + 1]);
            ffma2(acc2[0], b0[u], v2);
            ffma2(acc2[1], b1[u], v2);
            ffma2(acc2[2], b2[u], v2);
            ffma2(acc2[3], b3[u], v2);
        }
#pragma unroll
        for (int r = 0; r < 4; r++)
            g_att[(tok0 + i0 + r) * 256 + h * 32 + l] = hsum2(acc2[r]);
    }
}

// ---------------------------------------------------------------------------
extern "C" void kernel_launch(void* const* d_in, const int* in_sizes, int n_in,
                              void* d_out, int out_size)
{
    const float* feats    = (const float*)d_in[0];
    const float* n_coords = (const float*)d_in[1];
    const float* qkv_w    = (const float*)d_in[2];
    const float* qkv_b    = (const float*)d_in[3];
    const float* qx       = (const float*)d_in[4];
    const float* kx       = (const float*)d_in[5];
    const float* vx       = (const float*)d_in[6];
    const float* qr       = (const float*)d_in[7];
    const float* kr       = (const float*)d_in[8];
    const float* vr       = (const float*)d_in[9];
    const float* pw       = (const float*)d_in[10];
    const float* pb       = (const float*)d_in[11];
    float* out = (float*)d_out;

    cudaFuncSetAttribute(attn_kernel,
                         cudaFuncAttributeMaxDynamicSharedMemorySize,
                         SMEM_BYTES);

    qkv_gemm_kernel<<<dim3(64, 6), 256>>>(feats, qkv_w, qkv_b);
    attn_kernel<<<dim3(NW, HH), 512, SMEM_BYTES>>>(n_coords, qx, kx, vx,
                                                   qr, kr, vr);
    proj_gemm_kernel<<<dim3(64, 2), 256>>>(pw, pb, out);
}

// round 7
// speedup vs baseline: 1.1751x; 1.0819x over previous
#include <cuda_runtime.h>
#include <cuda_bf16.h>
#include <math.h>

// Problem constants
#define NTOK   8192
#define DIM    256
#define HH     8
#define HD     32
#define WW     64
#define NW     128          // NTOK / WW
#define T6     216          // 3*40 + 3*32
#define QSCALE 0.17677669529663687f   // 32^-0.5

typedef unsigned long long u64;

// ---- packed f32x2 helpers (sm_100+) ----
__device__ __forceinline__ void ffma2(u64 &c, u64 a, u64 b) {
    asm("fma.rn.f32x2 %0, %1, %2, %0;" : "+l"(c) : "l"(a), "l"(b));
}
__device__ __forceinline__ u64 pk2(float lo, float hi) {
    u64 r; asm("mov.b64 %0, {%1, %2};" : "=l"(r) : "f"(lo), "f"(hi)); return r;
}
__device__ __forceinline__ float2 up2(u64 v) {
    float2 r; asm("mov.b64 {%0, %1}, %2;" : "=f"(r.x), "=f"(r.y) : "l"(v)); return r;
}
__device__ __forceinline__ float hsum2(u64 v) { float2 p = up2(v); return p.x + p.y; }

// Global scratch (static device allocations -- allowed)
__device__ float g_q[NTOK * DIM];
__device__ float g_k[NTOK * DIM];
__device__ float g_v[NTOK * DIM];
__device__ float g_att[NTOK * DIM];

// ---------------------------------------------------------------------------
// QKV GEMM: BM=128 BN=128 BK=16, 256 threads, 8x8 via f32x2, double-buffered.
// ---------------------------------------------------------------------------
__global__ __launch_bounds__(256) void qkv_gemm_kernel(
    const float* __restrict__ A, const float* __restrict__ Wt,
    const float* __restrict__ bias)
{
    __shared__ __align__(16) float As[2][16][132];
    __shared__ __align__(16) float Bs[2][16][132];
    const int m0 = blockIdx.x * 128, n0 = blockIdx.y * 128;
    const int tid = threadIdx.x;
    const int tx = tid & 15, ty = tid >> 4;
    const int lr = tid >> 1, lc = (tid & 1) * 8;

    u64 c2[8][4];
#pragma unroll
    for (int i = 0; i < 8; i++)
#pragma unroll
        for (int j = 0; j < 4; j++) c2[i][j] = pk2(0.f, 0.f);

    const float* Arow = A  + (m0 + lr) * 256 + lc;
    const float* Brow = Wt + (n0 + lr) * 256 + lc;

    // preload k-tile 0 into buffer 0
    {
        float4 a0 = *(const float4*)(Arow);
        float4 a1 = *(const float4*)(Arow + 4);
        float4 b0 = *(const float4*)(Brow);
        float4 b1 = *(const float4*)(Brow + 4);
        As[0][lc + 0][lr] = a0.x; As[0][lc + 1][lr] = a0.y;
        As[0][lc + 2][lr] = a0.z; As[0][lc + 3][lr] = a0.w;
        As[0][lc + 4][lr] = a1.x; As[0][lc + 5][lr] = a1.y;
        As[0][lc + 6][lr] = a1.z; As[0][lc + 7][lr] = a1.w;
        Bs[0][lc + 0][lr] = b0.x; Bs[0][lc + 1][lr] = b0.y;
        Bs[0][lc + 2][lr] = b0.z; Bs[0][lc + 3][lr] = b0.w;
        Bs[0][lc + 4][lr] = b1.x; Bs[0][lc + 5][lr] = b1.y;
        Bs[0][lc + 6][lr] = b1.z; Bs[0][lc + 7][lr] = b1.w;
    }
    __syncthreads();

    for (int step = 0; step < 16; step++) {
        const int cur = step & 1, nxt = cur ^ 1;
        float4 na0, na1, nb0, nb1;
        if (step < 15) {
            const int kk = (step + 1) * 16;
            na0 = *(const float4*)(Arow + kk);
            na1 = *(const float4*)(Arow + kk + 4);
            nb0 = *(const float4*)(Brow + kk);
            nb1 = *(const float4*)(Brow + kk + 4);
        }
#pragma unroll
        for (int k = 0; k < 16; k++) {
            float4 av0 = *(const float4*)&As[cur][k][ty * 4];
            float4 av1 = *(const float4*)&As[cur][k][64 + ty * 4];
            ulonglong2 bl = *(const ulonglong2*)&Bs[cur][k][tx * 4];
            ulonglong2 bh = *(const ulonglong2*)&Bs[cur][k][64 + tx * 4];
            u64 bb[4] = {bl.x, bl.y, bh.x, bh.y};
            float aa[8] = {av0.x, av0.y, av0.z, av0.w,
                           av1.x, av1.y, av1.z, av1.w};
#pragma unroll
            for (int i = 0; i < 8; i++) {
                u64 ad = pk2(aa[i], aa[i]);
#pragma unroll
                for (int j = 0; j < 4; j++) ffma2(c2[i][j], ad, bb[j]);
            }
        }
        if (step < 15) {
            As[nxt][lc + 0][lr] = na0.x; As[nxt][lc + 1][lr] = na0.y;
            As[nxt][lc + 2][lr] = na0.z; As[nxt][lc + 3][lr] = na0.w;
            As[nxt][lc + 4][lr] = na1.x; As[nxt][lc + 5][lr] = na1.y;
            As[nxt][lc + 6][lr] = na1.z; As[nxt][lc + 7][lr] = na1.w;
            Bs[nxt][lc + 0][lr] = nb0.x; Bs[nxt][lc + 1][lr] = nb0.y;
            Bs[nxt][lc + 2][lr] = nb0.z; Bs[nxt][lc + 3][lr] = nb0.w;
            Bs[nxt][lc + 4][lr] = nb1.x; Bs[nxt][lc + 5][lr] = nb1.y;
            Bs[nxt][lc + 6][lr] = nb1.z; Bs[nxt][lc + 7][lr] = nb1.w;
            __syncthreads();
        }
    }

#pragma unroll
    for (int i = 0; i < 8; i++) {
        int m = m0 + ((i < 4) ? (ty * 4 + i) : (64 + ty * 4 + i - 4));
#pragma unroll
        for (int g = 0; g < 2; g++) {
            int n = n0 + g * 64 + tx * 4;
            float2 p0 = up2(c2[i][g * 2]);
            float2 p1 = up2(c2[i][g * 2 + 1]);
            float4 b4 = *(const float4*)&bias[n];
            float4 o;
            o.x = p0.x + b4.x; o.y = p0.y + b4.y;
            o.z = p1.x + b4.z; o.w = p1.y + b4.w;
            int s = n >> 8, col = n & 255;
            float* dst;
            if (s == 0) {
                o.x *= QSCALE; o.y *= QSCALE; o.z *= QSCALE; o.w *= QSCALE;
                dst = g_q;
            } else if (s == 1) dst = g_k;
            else               dst = g_v;
            *(float4*)&dst[m * 256 + col] = o;
        }
    }
}

// ---------------------------------------------------------------------------
// Projection GEMM, same structure (double-buffered)
// ---------------------------------------------------------------------------
__global__ __launch_bounds__(256) void proj_gemm_kernel(
    const float* __restrict__ Wt, const float* __restrict__ bias,
    float* __restrict__ out)
{
    __shared__ __align__(16) float As[2][16][132];
    __shared__ __align__(16) float Bs[2][16][132];
    const int m0 = blockIdx.x * 128, n0 = blockIdx.y * 128;
    const int tid = threadIdx.x;
    const int tx = tid & 15, ty = tid >> 4;
    const int lr = tid >> 1, lc = (tid & 1) * 8;

    u64 c2[8][4];
#pragma unroll
    for (int i = 0; i < 8; i++)
#pragma unroll
        for (int j = 0; j < 4; j++) c2[i][j] = pk2(0.f, 0.f);

    const float* Arow = g_att + (m0 + lr) * 256 + lc;
    const float* Brow = Wt    + (n0 + lr) * 256 + lc;

    {
        float4 a0 = *(const float4*)(Arow);
        float4 a1 = *(const float4*)(Arow + 4);
        float4 b0 = *(const float4*)(Brow);
        float4 b1 = *(const float4*)(Brow + 4);
        As[0][lc + 0][lr] = a0.x; As[0][lc + 1][lr] = a0.y;
        As[0][lc + 2][lr] = a0.z; As[0][lc + 3][lr] = a0.w;
        As[0][lc + 4][lr] = a1.x; As[0][lc + 5][lr] = a1.y;
        As[0][lc + 6][lr] = a1.z; As[0][lc + 7][lr] = a1.w;
        Bs[0][lc + 0][lr] = b0.x; Bs[0][lc + 1][lr] = b0.y;
        Bs[0][lc + 2][lr] = b0.z; Bs[0][lc + 3][lr] = b0.w;
        Bs[0][lc + 4][lr] = b1.x; Bs[0][lc + 5][lr] = b1.y;
        Bs[0][lc + 6][lr] = b1.z; Bs[0][lc + 7][lr] = b1.w;
    }
    __syncthreads();

    for (int step = 0; step < 16; step++) {
        const int cur = step & 1, nxt = cur ^ 1;
        float4 na0, na1, nb0, nb1;
        if (step < 15) {
            const int kk = (step + 1) * 16;
            na0 = *(const float4*)(Arow + kk);
            na1 = *(const float4*)(Arow + kk + 4);
            nb0 = *(const float4*)(Brow + kk);
            nb1 = *(const float4*)(Brow + kk + 4);
        }
#pragma unroll
        for (int k = 0; k < 16; k++) {
            float4 av0 = *(const float4*)&As[cur][k][ty * 4];
            float4 av1 = *(const float4*)&As[cur][k][64 + ty * 4];
            ulonglong2 bl = *(const ulonglong2*)&Bs[cur][k][tx * 4];
            ulonglong2 bh = *(const ulonglong2*)&Bs[cur][k][64 + tx * 4];
            u64 bb[4] = {bl.x, bl.y, bh.x, bh.y};
            float aa[8] = {av0.x, av0.y, av0.z, av0.w,
                           av1.x, av1.y, av1.z, av1.w};
#pragma unroll
            for (int i = 0; i < 8; i++) {
                u64 ad = pk2(aa[i], aa[i]);
#pragma unroll
                for (int j = 0; j < 4; j++) ffma2(c2[i][j], ad, bb[j]);
            }
        }
        if (step < 15) {
            As[nxt][lc + 0][lr] = na0.x; As[nxt][lc + 1][lr] = na0.y;
            As[nxt][lc + 2][lr] = na0.z; As[nxt][lc + 3][lr] = na0.w;
            As[nxt][lc + 4][lr] = na1.x; As[nxt][lc + 5][lr] = na1.y;
            As[nxt][lc + 6][lr] = na1.z; As[nxt][lc + 7][lr] = na1.w;
            Bs[nxt][lc + 0][lr] = nb0.x; Bs[nxt][lc + 1][lr] = nb0.y;
            Bs[nxt][lc + 2][lr] = nb0.z; Bs[nxt][lc + 3][lr] = nb0.w;
            Bs[nxt][lc + 4][lr] = nb1.x; Bs[nxt][lc + 5][lr] = nb1.y;
            Bs[nxt][lc + 6][lr] = nb1.z; Bs[nxt][lc + 7][lr] = nb1.w;
            __syncthreads();
        }
    }

#pragma unroll
    for (int i = 0; i < 8; i++) {
        int m = m0 + ((i < 4) ? (ty * 4 + i) : (64 + ty * 4 + i - 4));
#pragma unroll
        for (int g = 0; g < 2; g++) {
            int n = n0 + g * 64 + tx * 4;
            float2 p0 = up2(c2[i][g * 2]);
            float2 p1 = up2(c2[i][g * 2 + 1]);
            float4 b4 = *(const float4*)&bias[n];
            float4 o;
            o.x = p0.x + b4.x; o.y = p0.y + b4.y;
            o.z = p1.x + b4.z; o.w = p1.y + b4.w;
            *(float4*)&out[m * 256 + n] = o;
        }
    }
}

// ---------------------------------------------------------------------------
// Attention kernel: one block per (window, head). 512 threads (16 warps).
// Shared layout (floats), total 53024 floats = 212096 B:
//   scw   [384]       @ 0
//   sq    [64*33]     @ 384
//   sk    [64*33]     @ 2496
//   svT   [32*65]     @ 4608    (d-major)
//   stabQ [216*32]    @ 6688    (dead after Dq/Dk; s_idx u64[4096] aliases)
//   stabK [216*32]    @ 13600
//   sdq   [64*220]    @ 20512   (dead after logits; satT [216*68] aliases)
//   sdk   [64*220]    @ 34592   (dead after logits; vtabT @35200 str 217)
//   slogT [64*68]     @ 48672   (j-major: slogT[j][i])
// ---------------------------------------------------------------------------
#define SM_FLOATS 53024
#define SMEM_BYTES (SM_FLOATS * 4)

__global__ __launch_bounds__(512) void attn_kernel(
    const float* __restrict__ n_coords,
    const float* __restrict__ qx, const float* __restrict__ kx,
    const float* __restrict__ vx,
    const float* __restrict__ qr, const float* __restrict__ kr,
    const float* __restrict__ vr)
{
    extern __shared__ __align__(16) float sm[];
    float* scw   = sm;
    float* sq    = sm + 384;     // stride 33
    float* sk    = sm + 2496;    // stride 33
    float* svT   = sm + 4608;    // stride 65
    float* stabQ = sm + 6688;
    float* stabK = sm + 13600;
    float* sdq   = sm + 20512;   // stride 220
    float* sdk   = sm + 34592;   // stride 220
    float* slogT = sm + 48672;   // stride 68, [j][i]
    float* satT  = sm + 20512;   // stride 68, [t][i]   (aliases sdq after logits)
    float* vtabT = sm + 35200;   // stride 217, [d][t]  (aliases sdk tail)
    u64*   s_idx = (u64*)(sm + 6688);   // u64[4096] over stabQ/K (after Dq/Dk)

    const int nb = blockIdx.x, h = blockIdx.y;
    const int tid = threadIdx.x;
    const int l = tid & 31, w = tid >> 5;
    const int tok0 = nb * WW;

    // ---- load coords, q, k, v(T), both tables ----
    for (int s = tid; s < WW * 6; s += 512) {
        int i = s / 6, c = s % 6;
        scw[s] = n_coords[(tok0 + i) * 6 + c] * (c < 3 ? 4.0f : 8.0f);
    }
    for (int s = tid; s < WW * HD; s += 512) {
        int i = s >> 5, d = s & 31;
        int g = (tok0 + i) * 256 + h * 32 + d;
        sq[i * 33 + d]  = g_q[g];
        sk[i * 33 + d]  = g_k[g];
        svT[d * 65 + i] = g_v[g];
    }
    for (int s = tid; s < T6 * HD; s += 512) {
        int t = s >> 5, d = s & 31;
        stabQ[s] = (t < 120) ? qx[(t * 8 + h) * 32 + d]
                             : qr[((t - 120) * 8 + h) * 32 + d];
        stabK[s] = (t < 120) ? kx[(t * 8 + h) * 32 + d]
                             : kr[((t - 120) * 8 + h) * 32 + d];
    }
    __syncthreads();

    // ---- Dq / Dk : i = tid&63, each of 8 groups covers 27 t ----
    {
        const int i = tid & 63, grp = tid >> 6;
        const int t0 = grp * 27, t1 = t0 + 27;
        u64 a2[16];
#pragma unroll
        for (int d2 = 0; d2 < 16; d2++)
            a2[d2] = pk2(sq[i * 33 + 2 * d2], sq[i * 33 + 2 * d2 + 1]);
        for (int t = t0; t < t1; t++) {
            const ulonglong2* tv = (const ulonglong2*)(stabQ + t * 32);
            u64 acc = pk2(0.f, 0.f);
#pragma unroll
            for (int d4 = 0; d4 < 8; d4++) {
                ulonglong2 tt = tv[d4];
                ffma2(acc, a2[2 * d4],     tt.x);
                ffma2(acc, a2[2 * d4 + 1], tt.y);
            }
            sdq[i * 220 + t] = hsum2(acc);
        }
#pragma unroll
        for (int d2 = 0; d2 < 16; d2++)
            a2[d2] = pk2(sk[i * 33 + 2 * d2], sk[i * 33 + 2 * d2 + 1]);
        for (int t = t0; t < t1; t++) {
            const ulonglong2* tv = (const ulonglong2*)(stabK + t * 32);
            u64 acc = pk2(0.f, 0.f);
#pragma unroll
            for (int d4 = 0; d4 < 8; d4++) {
                ulonglong2 tt = tv[d4];
                ffma2(acc, a2[2 * d4],     tt.x);
                ffma2(acc, a2[2 * d4 + 1], tt.y);
            }
            sdk[i * 220 + t] = hsum2(acc);
        }
    }
    __syncthreads();

    // ---- logits (4 rows per warp), write slogT[j][i] + s_idx ----
    {
        const int basec[6] = {0, 40, 80, 120, 152, 184};
        const int offc[6]  = {20, 20, 20, 16, 16, 16};
        const int hic[6]   = {39, 39, 39, 31, 31, 31};
#pragma unroll
        for (int r = 0; r < 4; r++) {
            int i = w * 4 + r;
            float ci[6];
#pragma unroll
            for (int c = 0; c < 6; c++) ci[c] = scw[i * 6 + c];
            u64 q2[16];
#pragma unroll
            for (int d2 = 0; d2 < 16; d2++)
                q2[d2] = pk2(sq[i * 33 + 2 * d2], sq[i * 33 + 2 * d2 + 1]);
#pragma unroll
            for (int jj = 0; jj < 2; jj++) {
                int j = l + jj * 32;
                const float* krow = sk + j * 33;
                u64 acc2 = pk2(0.f, 0.f);
#pragma unroll
                for (int d2 = 0; d2 < 16; d2++)
                    ffma2(acc2, q2[d2], pk2(krow[2 * d2], krow[2 * d2 + 1]));
                float acc = hsum2(acc2);
                u64 pack = 0;
#pragma unroll
                for (int c = 0; c < 6; c++) {
                    int id = (int)floorf(ci[c] - scw[j * 6 + c]) + offc[c];
                    id = min(max(id, 0), hic[c]);
                    int t = basec[c] + id;
                    acc += sdq[i * 220 + t] + sdk[j * 220 + t];
                    pack |= (u64)t << (8 * c);
                }
                slogT[j * 68 + i] = acc;
                s_idx[i * 64 + j] = pack;
            }
        }
    }
    __syncthreads();   // logits reads of sdq/sdk complete; satT/vtabT may alias

    // ---- zero satT bins, load v-table (transposed, stride 217) ----
    for (int s = tid; s < T6 * 68; s += 512) satT[s] = 0.f;
    for (int s = tid; s < T6 * HD; s += 512) {
        int t = s >> 5, d = s & 31;
        float val = (t < 120) ? vx[(t * 8 + h) * 32 + d]
                              : vr[((t - 120) * 8 + h) * 32 + d];
        vtabT[d * 217 + t] = val;
    }
    __syncthreads();

    // ---- softmax (own rows per warp), normalize in slogT ----
#pragma unroll
    for (int r = 0; r < 4; r++) {
        int i = w * 4 + r;
        float v0 = slogT[l * 68 + i], v1 = slogT[(l + 32) * 68 + i];
        float m = fmaxf(v0, v1);
#pragma unroll
        for (int o = 16; o > 0; o >>= 1)
            m = fmaxf(m, __shfl_xor_sync(0xffffffffu, m, o));
        float e0 = __expf(v0 - m), e1 = __expf(v1 - m);
        float s = e0 + e1;
#pragma unroll
        for (int o = 16; o > 0; o >>= 1)
            s += __shfl_xor_sync(0xffffffffu, s, o);
        float inv = 1.0f / s;
        slogT[l * 68 + i]        = e0 * inv;
        slogT[(l + 32) * 68 + i] = e1 * inv;
    }
    __syncwarp();

    // ---- atomic-free binning: lane owns (row, coord) -> disjoint bins ----
    if (l < 24) {
        int r = l / 6, c = l % 6;
        int i = w * 4 + r;
        const u64* ip = s_idx + i * 64;
        const int sh = 8 * c;
        for (int j = 0; j < 64; j++) {
            int t = (int)((ip[j] >> sh) & 255u);
            satT[t * 68 + i] += slogT[j * 68 + i];
        }
    }
    __syncwarp();

    // ---- out[i][d] = attn @ v + at @ vtab ----
    // lane = d; one bcast LDS.128 serves all 4 rows; f32x2 packs row-pairs.
    {
        const int i0 = w * 4;
        u64 acc01 = pk2(0.f, 0.f), acc23 = pk2(0.f, 0.f);
        const float* svrow = svT + l * 65;
#pragma unroll 8
        for (int j = 0; j < 64; j++) {
            float4 a4 = *(const float4*)&slogT[j * 68 + i0];
            float v = svrow[j];
            u64 vd = pk2(v, v);
            ffma2(acc01, pk2(a4.x, a4.y), vd);
            ffma2(acc23, pk2(a4.z, a4.w), vd);
        }
        const float* vtrow = vtabT + l * 217;
#pragma unroll 8
        for (int t = 0; t < T6; t++) {
            float4 a4 = *(const float4*)&satT[t * 68 + i0];
            float v = vtrow[t];
            u64 vd = pk2(v, v);
            ffma2(acc01, pk2(a4.x, a4.y), vd);
            ffma2(acc23, pk2(a4.z, a4.w), vd);
        }
        float2 o01 = up2(acc01), o23 = up2(acc23);
        const int ob = (tok0 + i0) * 256 + h * 32 + l;
        g_att[ob]           = o01.x;
        g_att[ob + 256]     = o01.y;
        g_att[ob + 512]     = o23.x;
        g_att[ob + 768]     = o23.y;
    }
}

// ---------------------------------------------------------------------------
extern "C" void kernel_launch(void* const* d_in, const int* in_sizes, int n_in,
                              void* d_out, int out_size)
{
    const float* feats    = (const float*)d_in[0];
    const float* n_coords = (const float*)d_in[1];
    const float* qkv_w    = (const float*)d_in[2];
    const float* qkv_b    = (const float*)d_in[3];
    const float* qx       = (const float*)d_in[4];
    const float* kx       = (const float*)d_in[5];
    const float* vx       = (const float*)d_in[6];
    const float* qr       = (const float*)d_in[7];
    const float* kr       = (const float*)d_in[8];
    const float* vr       = (const float*)d_in[9];
    const float* pw       = (const float*)d_in[10];
    const float* pb       = (const float*)d_in[11];
    float* out = (float*)d_out;

    cudaFuncSetAttribute(attn_kernel,
                         cudaFuncAttributeMaxDynamicSharedMemorySize,
                         SMEM_BYTES);

    qkv_gemm_kernel<<<dim3(64, 6), 256>>>(feats, qkv_w, qkv_b);
    attn_kernel<<<dim3(NW, HH), 512, SMEM_BYTES>>>(n_coords, qx, kx, vx,
                                                   qr, kr, vr);
    proj_gemm_kernel<<<dim3(64, 2), 256>>>(pw, pb, out);
}